// round 8
// baseline (speedup 1.0000x reference)
#include <cuda_runtime.h>
#include <cuda_fp16.h>
#include <math.h>

// ContractiveMessageBlock — Round 7: fp16 2-pass HMMA with widened RAW distance
// (all-B-loads, then ah-pass, then al-pass per ks step). Rest identical to R6.

#define E_TOT   200000
#define FEAT    128
#define TM      128
#define NBLK    ((E_TOT + TM - 1) / TM)   // 1563
#define NB      2000
#define NRBF    20
#define PI_OVER_CUT 0.62831853071795864769f

typedef unsigned long long u64;
typedef unsigned int u32;

// ---------------- f32x2 / misc helpers ----------------
__device__ __forceinline__ u64 fma2(u64 a, u64 b, u64 c) {
    u64 d; asm("fma.rn.f32x2 %0, %1, %2, %3;" : "=l"(d) : "l"(a), "l"(b), "l"(c)); return d;
}
__device__ __forceinline__ u64 mul2(u64 a, u64 b) {
    u64 d; asm("mul.rn.f32x2 %0, %1, %2;" : "=l"(d) : "l"(a), "l"(b)); return d;
}
__device__ __forceinline__ u64 add2(u64 a, u64 b) {
    u64 d; asm("add.rn.f32x2 %0, %1, %2;" : "=l"(d) : "l"(a), "l"(b)); return d;
}
__device__ __forceinline__ u64 dup2(float x) {
    u64 d; asm("mov.b64 %0, {%1, %1};" : "=l"(d) : "f"(x)); return d;
}
__device__ __forceinline__ u64 pk2(float a, float b) {
    u64 d; asm("mov.b64 %0, {%1, %2};" : "=l"(d) : "f"(a), "f"(b)); return d;
}
__device__ __forceinline__ void unpack2(u64 a, float& lo, float& hi) {
    asm("mov.b64 {%0, %1}, %2;" : "=f"(lo), "=f"(hi) : "l"(a));
}
__device__ __forceinline__ void red_add_v4(float* p, float a, float b, float c, float d) {
    asm volatile("red.global.add.v4.f32 [%0], {%1, %2, %3, %4};"
                 :: "l"(p), "f"(a), "f"(b), "f"(c), "f"(d) : "memory");
}
__device__ __forceinline__ u32 smem_u32(const void* p) {
    u32 a; asm("{ .reg .u64 t; cvta.to.shared.u64 t, %1; cvt.u32.u64 %0, t; }"
               : "=r"(a) : "l"(p));
    return a;
}
// fp16 split of an f32 pair: hi = h2(x,y), lo = h2(residual)
__device__ __forceinline__ void split2h(float x, float y, u32& hi, u32& lo) {
    __half2 h = __floats2half2_rn(x, y);
    float rx = x - __half2float(__low2half(h));
    float ry = y - __half2float(__high2half(h));
    __half2 l = __floats2half2_rn(rx, ry);
    hi = *(u32*)&h; lo = *(u32*)&l;
}
__device__ __forceinline__ void cpa16(u32 s, const void* g) {
    asm volatile("cp.async.cg.shared.global [%0], [%1], 16;" :: "r"(s), "l"(g));
}
__device__ __forceinline__ void cpa_commit() {
    asm volatile("cp.async.commit_group;" ::: "memory");
}
__device__ __forceinline__ void cpa_wait0() {
    asm volatile("cp.async.wait_group 0;" ::: "memory");
}

// ---------------- mma / ldmatrix ----------------
__device__ __forceinline__ void ldsm4(u32* r, u32 addr) {
    asm volatile("ldmatrix.sync.aligned.m8n8.x4.shared.b16 {%0,%1,%2,%3}, [%4];"
                 : "=r"(r[0]), "=r"(r[1]), "=r"(r[2]), "=r"(r[3]) : "r"(addr));
}
__device__ __forceinline__ void mma16816(float* d, const u32* a, u32 b0, u32 b1) {
    asm volatile(
        "mma.sync.aligned.m16n8k16.row.col.f32.f16.f16.f32 "
        "{%0,%1,%2,%3}, {%4,%5,%6,%7}, {%8,%9}, {%0,%1,%2,%3};"
        : "+f"(d[0]), "+f"(d[1]), "+f"(d[2]), "+f"(d[3])
        : "r"(a[0]), "r"(a[1]), "r"(a[2]), "r"(a[3]), "r"(b0), "r"(b1));
}

// fp16 tile [128 rows][128 k]: 16B granules, XOR swizzle.
__device__ __host__ __forceinline__ int toff(int row, int kg) {
    return row * 256 + (((kg ^ (row & 7)) & 15) << 4);
}
// fp32 scratch [128 e][128 c], word index with 4-word-granule XOR swizzle.
__device__ __forceinline__ int scr_w(int e, int c) {
    return e * 128 + (((((c >> 2)) ^ (e & 7)) & 31) << 2) + (c & 3);
}

// ---------------- global scratch ----------------
__device__ __align__(16) float g_acc_s[NB * FEAT];      // [bin][f]
__device__ __align__(16) float g_acc_v[NB * 3 * FEAT];  // [bin][x][f]
__device__ float g_cnt[NB];
__device__ __align__(16) unsigned char g_W1[32768];          // fp16 tile
__device__ __align__(16) unsigned char g_W2[3 * 32768];      // fp16 tiles

// ---------------- smem offsets (bytes) ----------------
#define OFF_AHI  0        // 32768  A then H, fp16 hi
#define OFF_ALO  32768    // 32768  A then H, fp16 lo (split residual)
#define OFF_W    65536    // 32768  current W tile (fp16)
#define OFF_SCR  98304    // 65536  fp32 D dump [128][128]
#define OFF_RBF  163840   // 10240  rbf [20][128]
#define OFF_UNIT 174080   // 1536   unit [3][128]
#define OFF_ENV  175616   // 512
#define OFF_BIN  176128   // 512 (int)
#define SMEM_BYTES 176640

__global__ void cmb_zero() {
    int i = blockIdx.x * 256 + threadIdx.x;
    if (i < NB * FEAT)     g_acc_s[i] = 0.0f;
    if (i < NB * 3 * FEAT) g_acc_v[i] = 0.0f;
    if (i < NB)            g_cnt[i]   = 0.0f;
}

// W1/W2 -> single fp16 tiles in swizzled [n][k] layout (B operand, TN gemm).
__global__ void cmb_prep(const float* __restrict__ W1, const float* __restrict__ W2) {
    int i = blockIdx.x * 256 + threadIdx.x;     // 0..65535
    if (i < 16384) {
        int n = i & 127, k = i >> 7;
        float v = W1[k * 128 + n];
        int off = toff(n, k >> 3) + (k & 7) * 2;
        *(__half*)(g_W1 + off) = __float2half_rn(v);
    } else if (i < 65536) {
        int r = i - 16384;
        int c = r >> 14;
        int t = r & 16383;
        int n = t & 127, k = t >> 7;
        float v = W2[k * 384 + c * 128 + n];
        int off = c * 32768 + toff(n, k >> 3) + (k & 7) * 2;
        *(__half*)(g_W2 + off) = __float2half_rn(v);
    }
}

// Issue cp.async for one W tile (32KB).
__device__ __forceinline__ void copyW_async(u32 sb, const unsigned char* g, int tid) {
    u32 d = sb + OFF_W;
    #pragma unroll
    for (int t = 0; t < 8; t++) {
        int i = tid + t * 256;
        cpa16(d + i * 16, g + i * 16);
    }
    cpa_commit();
}

// 2-pass fp16 split GEMM with widened RAW distance:
// per ks: load ah, al, all 8 B quads; then ah-pass (16 mma over 16 accs);
// then al-pass (16 mma). Same per-acc op order as R6 -> bit-identical results.
__device__ __forceinline__ void gemm_tile(u32 aHi, u32 aLo, u32 bW,
                                          int m0, int lane, float acc[16][4]) {
    const int r  = lane & 7;
    const int hf = (lane >> 3) & 1;
    const int kq = lane >> 4;
    const int arow = m0 + hf * 8 + r;
    const int brow = hf * 8 + r;
    #pragma unroll
    for (int ks = 0; ks < 8; ks++) {
        int kg = ks * 2 + kq;
        u32 ah[4], al[4];
        u32 aoff = (u32)toff(arow, kg);
        ldsm4(ah, aHi + aoff);
        ldsm4(al, aLo + aoff);
        u32 b[8][4];
        #pragma unroll
        for (int ng = 0; ng < 8; ng++)
            ldsm4(b[ng], bW + (u32)toff(ng * 16 + brow, kg));
        #pragma unroll
        for (int ng = 0; ng < 8; ng++) {
            mma16816(acc[2 * ng],     ah, b[ng][0], b[ng][2]);
            mma16816(acc[2 * ng + 1], ah, b[ng][1], b[ng][3]);
        }
        #pragma unroll
        for (int ng = 0; ng < 8; ng++) {
            mma16816(acc[2 * ng],     al, b[ng][0], b[ng][2]);
            mma16816(acc[2 * ng + 1], al, b[ng][1], b[ng][3]);
        }
    }
}

__device__ __forceinline__ void dump_all(float* scr, const float acc[16][4],
                                         int m0, int lane) {
    const int r0 = m0 + (lane >> 2);
    const int cb = (lane & 3) * 2;
    #pragma unroll
    for (int ng = 0; ng < 8; ng++)
        #pragma unroll
        for (int s = 0; s < 2; s++) {
            int c = ng * 16 + s * 8 + cb;
            const float* a = acc[2 * ng + s];
            *(float2*)&scr[scr_w(r0, c)]     = make_float2(a[0], a[1]);
            *(float2*)&scr[scr_w(r0 + 8, c)] = make_float2(a[2], a[3]);
        }
}

// Fused epilogue for chunk C. Fully unrolled over 16 edges so st0 stays in regs.
template <int C>
__device__ __forceinline__ void epilogue(
    const float* sScr, const float* sRbfT, const float* sUnit,
    const float* sEnv, const int* sBin,
    const float* __restrict__ v_i, const float* __restrict__ Wr_g,
    const float* __restrict__ b2, const float* __restrict__ br,
    long e0, int nvalid, int tid, float st0[16][4])
{
    const int j0  = (tid & 31) * 4;
    const int ebl = (tid >> 5) * 16;
    u64 wra[NRBF], wrb[NRBF];
    #pragma unroll
    for (int n = 0; n < NRBF; n++) {
        float4 w = *(const float4*)&Wr_g[n * 384 + C * 128 + j0];
        wra[n] = pk2(w.x, w.y); wrb[n] = pk2(w.z, w.w);
    }
    float4 b2v = *(const float4*)&b2[C * 128 + j0];
    float4 brv = *(const float4*)&br[C * 128 + j0];
    u64 b2a = pk2(b2v.x, b2v.y), b2b = pk2(b2v.z, b2v.w);
    u64 bra = pk2(brv.x, brv.y), brb = pk2(brv.z, brv.w);

    #pragma unroll
    for (int e = 0; e < 16; e++) {
        int ei = ebl + e;
        u64 w0 = bra, w1 = brb;
        #pragma unroll
        for (int n = 0; n < NRBF; n++) {
            u64 f = dup2(sRbfT[n * 128 + ei]);
            w0 = fma2(f, wra[n], w0);
            w1 = fma2(f, wrb[n], w1);
        }
        float4 d = *(const float4*)&sScr[scr_w(ei, j0)];
        u64 envd = dup2(sEnv[ei]);
        u64 i01 = mul2(add2(pk2(d.x, d.y), b2a), mul2(w0, envd));
        u64 i23 = mul2(add2(pk2(d.z, d.w), b2b), mul2(w1, envd));
        float i0, i1, i2, i3;
        unpack2(i01, i0, i1); unpack2(i23, i2, i3);

        if (C == 0) {
            st0[e][0] = i0; st0[e][1] = i1; st0[e][2] = i2; st0[e][3] = i3;
        } else if (C == 1) {
            if (ei < nvalid) {
                int bin = sBin[ei];
                red_add_v4(&g_acc_s[bin * FEAT + j0], i0, i1, i2, i3);
            }
        } else {
            if (ei < nvalid) {
                int bin = sBin[ei];
                const float4* vg =
                    (const float4*)(v_i + ((size_t)(e0 + ei) * FEAT + j0) * 3);
                float4 va = vg[0], vb = vg[1], vc2 = vg[2];
                float vf[12] = { va.x, va.y, va.z, va.w,
                                 vb.x, vb.y, vb.z, vb.w,
                                 vc2.x, vc2.y, vc2.z, vc2.w };
                float uu[3] = { sUnit[ei], sUnit[128 + ei], sUnit[256 + ei] };
                #pragma unroll
                for (int x = 0; x < 3; x++)
                    red_add_v4(&g_acc_v[bin * 3 * FEAT + x * FEAT + j0],
                        fmaf(i0, uu[x], st0[e][0] * vf[0 + x]),
                        fmaf(i1, uu[x], st0[e][1] * vf[3 + x]),
                        fmaf(i2, uu[x], st0[e][2] * vf[6 + x]),
                        fmaf(i3, uu[x], st0[e][3] * vf[9 + x]));
            }
        }
    }
}

__global__ void __launch_bounds__(256, 1)
cmb_main(const float* __restrict__ s_i, const float* __restrict__ v_i,
         const float* __restrict__ r_iI, const float* __restrict__ b1,
         const float* __restrict__ b2, const float* __restrict__ Wr_g,
         const float* __restrict__ br, const int* __restrict__ mapping)
{
    extern __shared__ char smem[];
    const u32 sb = smem_u32(smem);
    float* sScr  = (float*)(smem + OFF_SCR);
    float* sRbfT = (float*)(smem + OFF_RBF);
    float* sUnit = (float*)(smem + OFF_UNIT);
    float* sEnv  = (float*)(smem + OFF_ENV);
    int*   sBin  = (int*)(smem + OFF_BIN);

    const int tid  = threadIdx.x;
    const int lane = tid & 31;
    const int m0   = (tid >> 5) * 16;
    const long e0  = (long)blockIdx.x * TM;
    const int nvalid = (int)min((long)TM, (long)E_TOT - e0);

    // ---- W1 prefetch (cp.async) ----
    copyW_async(sb, g_W1, tid);

    // ---- A tile: s_i -> fp16 hi/lo (split) swizzled ----
    for (int i = tid; i < 2048; i += 256) {
        int row = i >> 4, kg = i & 15;
        float4 va, vb;
        if (row < nvalid) {
            const float4* g = (const float4*)(s_i + ((size_t)(e0 + row)) * FEAT + kg * 8);
            va = g[0]; vb = g[1];
        } else {
            va = make_float4(0.f, 0.f, 0.f, 0.f); vb = va;
        }
        u32 h0, l0, h1, l1, h2, l2, h3, l3;
        split2h(va.x, va.y, h0, l0); split2h(va.z, va.w, h1, l1);
        split2h(vb.x, vb.y, h2, l2); split2h(vb.z, vb.w, h3, l3);
        int off = toff(row, kg);
        *(uint4*)(smem + OFF_AHI + off) = make_uint4(h0, h1, h2, h3);
        *(uint4*)(smem + OFF_ALO + off) = make_uint4(l0, l1, l2, l3);
    }
    // ---- per-edge preprocess ----
    if (tid < TM) {
        int e = tid;
        if (e < nvalid) {
            long eg = e0 + e;
            float r0 = r_iI[eg * 3 + 0], r1 = r_iI[eg * 3 + 1], r2 = r_iI[eg * 3 + 2];
            float d = sqrtf(r0 * r0 + r1 * r1 + r2 * r2 + 3e-8f);
            float id = 1.0f / d;
            sUnit[0 * 128 + e] = r0 * id;
            sUnit[1 * 128 + e] = r1 * id;
            sUnit[2 * 128 + e] = r2 * id;
            sEnv[e] = (d < 5.0f) ? 0.5f * (cosf(PI_OVER_CUT * d) + 1.0f) : 0.0f;
            float ang = PI_OVER_CUT * d;
            #pragma unroll
            for (int n = 0; n < NRBF; n++)
                sRbfT[n * 128 + e] = sinf((float)(n + 1) * ang) * id;
            int b = mapping[eg];
            sBin[e] = b;
            atomicAdd(&g_cnt[b], 1.0f);
        } else {
            sUnit[e] = sUnit[128 + e] = sUnit[256 + e] = 0.0f;
            sEnv[e] = 0.0f; sBin[e] = 0;
            #pragma unroll
            for (int n = 0; n < NRBF; n++) sRbfT[n * 128 + e] = 0.0f;
        }
    }
    cpa_wait0();
    __syncthreads();

    float acc[16][4];
    float st0[16][4];

    // ---- GEMM1 ----
    #pragma unroll
    for (int q = 0; q < 16; q++)
        acc[q][0] = acc[q][1] = acc[q][2] = acc[q][3] = 0.0f;
    gemm_tile(sb + OFF_AHI, sb + OFF_ALO, sb + OFF_W, m0, lane, acc);
    __syncthreads();                  // all warps done reading W1
    copyW_async(sb, g_W2, tid);       // prefetch W2[0] under dump+silu
    dump_all(sScr, acc, m0, lane);
    __syncwarp();

    // ---- silu(D1 + b1) -> H fp16 hi/lo (own warp's rows) ----
    {
        const int j0  = (tid & 31) * 4;
        const int ebl = (tid >> 5) * 16;
        float4 bb = *(const float4*)&b1[j0];
        #pragma unroll 4
        for (int e = 0; e < 16; e++) {
            int ei = ebl + e;
            float4 d = *(float4*)&sScr[scr_w(ei, j0)];
            float x0 = d.x + bb.x, x1 = d.y + bb.y, x2 = d.z + bb.z, x3 = d.w + bb.w;
            float s0 = x0 / (1.0f + __expf(-x0));
            float s1 = x1 / (1.0f + __expf(-x1));
            float s2 = x2 / (1.0f + __expf(-x2));
            float s3 = x3 / (1.0f + __expf(-x3));
            u32 hA, lA, hB, lB;
            split2h(s0, s1, hA, lA); split2h(s2, s3, hB, lB);
            int off = toff(ei, j0 >> 3) + (j0 & 7) * 2;
            *(uint2*)(smem + OFF_AHI + off) = make_uint2(hA, hB);
            *(uint2*)(smem + OFF_ALO + off) = make_uint2(lA, lB);
        }
    }
    cpa_wait0();
    __syncthreads();   // H + W2[0] ready

    // ---- GEMM2 chunk 0 ----
    #pragma unroll
    for (int q = 0; q < 16; q++)
        acc[q][0] = acc[q][1] = acc[q][2] = acc[q][3] = 0.0f;
    gemm_tile(sb + OFF_AHI, sb + OFF_ALO, sb + OFF_W, m0, lane, acc);
    __syncthreads();
    copyW_async(sb, g_W2 + 32768, tid);
    dump_all(sScr, acc, m0, lane);
    __syncwarp();
    epilogue<0>(sScr, sRbfT, sUnit, sEnv, sBin, v_i, Wr_g, b2, br,
                e0, nvalid, tid, st0);
    cpa_wait0();
    __syncthreads();

    // ---- GEMM2 chunk 1 ----
    #pragma unroll
    for (int q = 0; q < 16; q++)
        acc[q][0] = acc[q][1] = acc[q][2] = acc[q][3] = 0.0f;
    gemm_tile(sb + OFF_AHI, sb + OFF_ALO, sb + OFF_W, m0, lane, acc);
    __syncthreads();
    copyW_async(sb, g_W2 + 65536, tid);
    dump_all(sScr, acc, m0, lane);
    __syncwarp();
    epilogue<1>(sScr, sRbfT, sUnit, sEnv, sBin, v_i, Wr_g, b2, br,
                e0, nvalid, tid, st0);
    cpa_wait0();
    __syncthreads();

    // ---- GEMM2 chunk 2 ----
    #pragma unroll
    for (int q = 0; q < 16; q++)
        acc[q][0] = acc[q][1] = acc[q][2] = acc[q][3] = 0.0f;
    gemm_tile(sb + OFF_AHI, sb + OFF_ALO, sb + OFF_W, m0, lane, acc);
    dump_all(sScr, acc, m0, lane);
    __syncwarp();
    epilogue<2>(sScr, sRbfT, sUnit, sEnv, sBin, v_i, Wr_g, b2, br,
                e0, nvalid, tid, st0);
}

__global__ void cmb_final(float* __restrict__ out) {
    int bin = blockIdx.x;
    int f   = threadIdx.x;
    float ic = 1.0f / fmaxf(g_cnt[bin], 1.0f);
    out[bin * FEAT + f] = g_acc_s[bin * FEAT + f] * ic;
    #pragma unroll
    for (int x = 0; x < 3; x++)
        out[NB * FEAT + bin * 384 + f * 3 + x] =
            g_acc_v[bin * 3 * FEAT + x * FEAT + f] * ic;
}

extern "C" void kernel_launch(void* const* d_in, const int* in_sizes, int n_in,
                              void* d_out, int out_size)
{
    const float* s_i     = (const float*)d_in[0];
    const float* v_i     = (const float*)d_in[1];
    const float* r_iI    = (const float*)d_in[2];
    const float* W1      = (const float*)d_in[3];
    const float* b1      = (const float*)d_in[4];
    const float* W2      = (const float*)d_in[5];
    const float* b2      = (const float*)d_in[6];
    const float* Wr      = (const float*)d_in[7];
    const float* br      = (const float*)d_in[8];
    const int*   mapping = (const int*)d_in[9];
    float* out = (float*)d_out;
    (void)in_sizes; (void)n_in; (void)out_size;

    cudaFuncSetAttribute((const void*)cmb_main,
                         cudaFuncAttributeMaxDynamicSharedMemorySize, SMEM_BYTES);

    cmb_prep<<<256, 256>>>(W1, W2);
    cmb_zero<<<(NB * 3 * FEAT + 255) / 256, 256>>>();
    cmb_main<<<NBLK, 256, SMEM_BYTES>>>(s_i, v_i, r_iI, b1, b2, Wr, br, mapping);
    cmb_final<<<NB, FEAT>>>(out);
}

// round 9
// speedup vs baseline: 1.2175x; 1.2175x over previous
#include <cuda_runtime.h>
#include <cuda_fp16.h>
#include <math.h>

// ContractiveMessageBlock — Round 8: single-pass fp16 HMMA GEMMs (A and W both
// fp16), sin-recurrence RBF. Epilogue/scatter machinery unchanged from R6.

#define E_TOT   200000
#define FEAT    128
#define TM      128
#define NBLK    ((E_TOT + TM - 1) / TM)   // 1563
#define NB      2000
#define NRBF    20
#define PI_OVER_CUT 0.62831853071795864769f

typedef unsigned long long u64;
typedef unsigned int u32;

// ---------------- f32x2 / misc helpers ----------------
__device__ __forceinline__ u64 fma2(u64 a, u64 b, u64 c) {
    u64 d; asm("fma.rn.f32x2 %0, %1, %2, %3;" : "=l"(d) : "l"(a), "l"(b), "l"(c)); return d;
}
__device__ __forceinline__ u64 mul2(u64 a, u64 b) {
    u64 d; asm("mul.rn.f32x2 %0, %1, %2;" : "=l"(d) : "l"(a), "l"(b)); return d;
}
__device__ __forceinline__ u64 add2(u64 a, u64 b) {
    u64 d; asm("add.rn.f32x2 %0, %1, %2;" : "=l"(d) : "l"(a), "l"(b)); return d;
}
__device__ __forceinline__ u64 dup2(float x) {
    u64 d; asm("mov.b64 %0, {%1, %1};" : "=l"(d) : "f"(x)); return d;
}
__device__ __forceinline__ u64 pk2(float a, float b) {
    u64 d; asm("mov.b64 %0, {%1, %2};" : "=l"(d) : "f"(a), "f"(b)); return d;
}
__device__ __forceinline__ void unpack2(u64 a, float& lo, float& hi) {
    asm("mov.b64 {%0, %1}, %2;" : "=f"(lo), "=f"(hi) : "l"(a));
}
__device__ __forceinline__ void red_add_v4(float* p, float a, float b, float c, float d) {
    asm volatile("red.global.add.v4.f32 [%0], {%1, %2, %3, %4};"
                 :: "l"(p), "f"(a), "f"(b), "f"(c), "f"(d) : "memory");
}
__device__ __forceinline__ u32 smem_u32(const void* p) {
    u32 a; asm("{ .reg .u64 t; cvta.to.shared.u64 t, %1; cvt.u32.u64 %0, t; }"
               : "=r"(a) : "l"(p));
    return a;
}
__device__ __forceinline__ void cpa16(u32 s, const void* g) {
    asm volatile("cp.async.cg.shared.global [%0], [%1], 16;" :: "r"(s), "l"(g));
}
__device__ __forceinline__ void cpa_commit() {
    asm volatile("cp.async.commit_group;" ::: "memory");
}
__device__ __forceinline__ void cpa_wait0() {
    asm volatile("cp.async.wait_group 0;" ::: "memory");
}

// ---------------- mma / ldmatrix ----------------
__device__ __forceinline__ void ldsm4(u32* r, u32 addr) {
    asm volatile("ldmatrix.sync.aligned.m8n8.x4.shared.b16 {%0,%1,%2,%3}, [%4];"
                 : "=r"(r[0]), "=r"(r[1]), "=r"(r[2]), "=r"(r[3]) : "r"(addr));
}
__device__ __forceinline__ void mma16816(float* d, const u32* a, u32 b0, u32 b1) {
    asm volatile(
        "mma.sync.aligned.m16n8k16.row.col.f32.f16.f16.f32 "
        "{%0,%1,%2,%3}, {%4,%5,%6,%7}, {%8,%9}, {%0,%1,%2,%3};"
        : "+f"(d[0]), "+f"(d[1]), "+f"(d[2]), "+f"(d[3])
        : "r"(a[0]), "r"(a[1]), "r"(a[2]), "r"(a[3]), "r"(b0), "r"(b1));
}

// fp16 tile [128 rows][128 k]: 16B granules, XOR swizzle.
__device__ __host__ __forceinline__ int toff(int row, int kg) {
    return row * 256 + (((kg ^ (row & 7)) & 15) << 4);
}
// fp32 scratch [128 e][128 c], word index with 4-word-granule XOR swizzle.
__device__ __forceinline__ int scr_w(int e, int c) {
    return e * 128 + (((((c >> 2)) ^ (e & 7)) & 31) << 2) + (c & 3);
}

// ---------------- global scratch ----------------
__device__ __align__(16) float g_acc_s[NB * FEAT];      // [bin][f]
__device__ __align__(16) float g_acc_v[NB * 3 * FEAT];  // [bin][x][f]
__device__ float g_cnt[NB];
__device__ __align__(16) unsigned char g_W1[32768];          // fp16 tile
__device__ __align__(16) unsigned char g_W2[3 * 32768];      // fp16 tiles

// ---------------- smem offsets (bytes) ----------------
#define OFF_A    0        // 32768  A then H, fp16
#define OFF_W    32768    // 32768  current W tile (fp16)
#define OFF_SCR  65536    // 65536  fp32 D dump [128][128]
#define OFF_RBF  131072   // 10240  rbf [20][128]
#define OFF_UNIT 141312   // 1536   unit [3][128]
#define OFF_ENV  142848   // 512
#define OFF_BIN  143360   // 512 (int)
#define SMEM_BYTES 143872

__global__ void cmb_zero() {
    int i = blockIdx.x * 256 + threadIdx.x;
    if (i < NB * FEAT)     g_acc_s[i] = 0.0f;
    if (i < NB * 3 * FEAT) g_acc_v[i] = 0.0f;
    if (i < NB)            g_cnt[i]   = 0.0f;
}

// W1/W2 -> fp16 tiles in swizzled [n][k] layout (B operand, TN gemm).
__global__ void cmb_prep(const float* __restrict__ W1, const float* __restrict__ W2) {
    int i = blockIdx.x * 256 + threadIdx.x;     // 0..65535
    if (i < 16384) {
        int n = i & 127, k = i >> 7;
        float v = W1[k * 128 + n];
        int off = toff(n, k >> 3) + (k & 7) * 2;
        *(__half*)(g_W1 + off) = __float2half_rn(v);
    } else if (i < 65536) {
        int r = i - 16384;
        int c = r >> 14;
        int t = r & 16383;
        int n = t & 127, k = t >> 7;
        float v = W2[k * 384 + c * 128 + n];
        int off = c * 32768 + toff(n, k >> 3) + (k & 7) * 2;
        *(__half*)(g_W2 + off) = __float2half_rn(v);
    }
}

// Issue cp.async for one W tile (32KB).
__device__ __forceinline__ void copyW_async(u32 sb, const unsigned char* g, int tid) {
    u32 d = sb + OFF_W;
    #pragma unroll
    for (int t = 0; t < 8; t++) {
        int i = tid + t * 256;
        cpa16(d + i * 16, g + i * 16);
    }
    cpa_commit();
}

// Single-pass fp16 GEMM: acc += A * B over warp stripe. 128 HMMA per call.
__device__ __forceinline__ void gemm_tile(u32 aT, u32 bW,
                                          int m0, int lane, float acc[16][4]) {
    const int r  = lane & 7;
    const int hf = (lane >> 3) & 1;
    const int kq = lane >> 4;
    const int arow = m0 + hf * 8 + r;
    const int brow = hf * 8 + r;
    #pragma unroll
    for (int ks = 0; ks < 8; ks++) {
        int kg = ks * 2 + kq;
        u32 a[4];
        ldsm4(a, aT + (u32)toff(arow, kg));
        #pragma unroll
        for (int ng = 0; ng < 8; ng++) {
            u32 b[4];
            ldsm4(b, bW + (u32)toff(ng * 16 + brow, kg));
            mma16816(acc[2 * ng],     a, b[0], b[2]);
            mma16816(acc[2 * ng + 1], a, b[1], b[3]);
        }
    }
}

__device__ __forceinline__ void dump_all(float* scr, const float acc[16][4],
                                         int m0, int lane) {
    const int r0 = m0 + (lane >> 2);
    const int cb = (lane & 3) * 2;
    #pragma unroll
    for (int ng = 0; ng < 8; ng++)
        #pragma unroll
        for (int s = 0; s < 2; s++) {
            int c = ng * 16 + s * 8 + cb;
            const float* a = acc[2 * ng + s];
            *(float2*)&scr[scr_w(r0, c)]     = make_float2(a[0], a[1]);
            *(float2*)&scr[scr_w(r0 + 8, c)] = make_float2(a[2], a[3]);
        }
}

// Fused epilogue for chunk C. Fully unrolled over 16 edges so st0 stays in regs.
template <int C>
__device__ __forceinline__ void epilogue(
    const float* sScr, const float* sRbfT, const float* sUnit,
    const float* sEnv, const int* sBin,
    const float* __restrict__ v_i, const float* __restrict__ Wr_g,
    const float* __restrict__ b2, const float* __restrict__ br,
    long e0, int nvalid, int tid, float st0[16][4])
{
    const int j0  = (tid & 31) * 4;
    const int ebl = (tid >> 5) * 16;
    u64 wra[NRBF], wrb[NRBF];
    #pragma unroll
    for (int n = 0; n < NRBF; n++) {
        float4 w = *(const float4*)&Wr_g[n * 384 + C * 128 + j0];
        wra[n] = pk2(w.x, w.y); wrb[n] = pk2(w.z, w.w);
    }
    float4 b2v = *(const float4*)&b2[C * 128 + j0];
    float4 brv = *(const float4*)&br[C * 128 + j0];
    u64 b2a = pk2(b2v.x, b2v.y), b2b = pk2(b2v.z, b2v.w);
    u64 bra = pk2(brv.x, brv.y), brb = pk2(brv.z, brv.w);

    #pragma unroll
    for (int e = 0; e < 16; e++) {
        int ei = ebl + e;
        u64 w0 = bra, w1 = brb;
        #pragma unroll
        for (int n = 0; n < NRBF; n++) {
            u64 f = dup2(sRbfT[n * 128 + ei]);
            w0 = fma2(f, wra[n], w0);
            w1 = fma2(f, wrb[n], w1);
        }
        float4 d = *(const float4*)&sScr[scr_w(ei, j0)];
        u64 envd = dup2(sEnv[ei]);
        u64 i01 = mul2(add2(pk2(d.x, d.y), b2a), mul2(w0, envd));
        u64 i23 = mul2(add2(pk2(d.z, d.w), b2b), mul2(w1, envd));
        float i0, i1, i2, i3;
        unpack2(i01, i0, i1); unpack2(i23, i2, i3);

        if (C == 0) {
            st0[e][0] = i0; st0[e][1] = i1; st0[e][2] = i2; st0[e][3] = i3;
        } else if (C == 1) {
            if (ei < nvalid) {
                int bin = sBin[ei];
                red_add_v4(&g_acc_s[bin * FEAT + j0], i0, i1, i2, i3);
            }
        } else {
            if (ei < nvalid) {
                int bin = sBin[ei];
                const float4* vg =
                    (const float4*)(v_i + ((size_t)(e0 + ei) * FEAT + j0) * 3);
                float4 va = vg[0], vb = vg[1], vc2 = vg[2];
                float vf[12] = { va.x, va.y, va.z, va.w,
                                 vb.x, vb.y, vb.z, vb.w,
                                 vc2.x, vc2.y, vc2.z, vc2.w };
                float uu[3] = { sUnit[ei], sUnit[128 + ei], sUnit[256 + ei] };
                #pragma unroll
                for (int x = 0; x < 3; x++)
                    red_add_v4(&g_acc_v[bin * 3 * FEAT + x * FEAT + j0],
                        fmaf(i0, uu[x], st0[e][0] * vf[0 + x]),
                        fmaf(i1, uu[x], st0[e][1] * vf[3 + x]),
                        fmaf(i2, uu[x], st0[e][2] * vf[6 + x]),
                        fmaf(i3, uu[x], st0[e][3] * vf[9 + x]));
            }
        }
    }
}

__global__ void __launch_bounds__(256, 1)
cmb_main(const float* __restrict__ s_i, const float* __restrict__ v_i,
         const float* __restrict__ r_iI, const float* __restrict__ b1,
         const float* __restrict__ b2, const float* __restrict__ Wr_g,
         const float* __restrict__ br, const int* __restrict__ mapping)
{
    extern __shared__ char smem[];
    const u32 sb = smem_u32(smem);
    float* sScr  = (float*)(smem + OFF_SCR);
    float* sRbfT = (float*)(smem + OFF_RBF);
    float* sUnit = (float*)(smem + OFF_UNIT);
    float* sEnv  = (float*)(smem + OFF_ENV);
    int*   sBin  = (int*)(smem + OFF_BIN);

    const int tid  = threadIdx.x;
    const int lane = tid & 31;
    const int m0   = (tid >> 5) * 16;
    const long e0  = (long)blockIdx.x * TM;
    const int nvalid = (int)min((long)TM, (long)E_TOT - e0);

    // ---- W1 prefetch (cp.async) ----
    copyW_async(sb, g_W1, tid);

    // ---- A tile: s_i -> fp16 swizzled ----
    for (int i = tid; i < 2048; i += 256) {
        int row = i >> 4, kg = i & 15;
        float4 va, vb;
        if (row < nvalid) {
            const float4* g = (const float4*)(s_i + ((size_t)(e0 + row)) * FEAT + kg * 8);
            va = g[0]; vb = g[1];
        } else {
            va = make_float4(0.f, 0.f, 0.f, 0.f); vb = va;
        }
        __half2 h0 = __floats2half2_rn(va.x, va.y);
        __half2 h1 = __floats2half2_rn(va.z, va.w);
        __half2 h2 = __floats2half2_rn(vb.x, vb.y);
        __half2 h3 = __floats2half2_rn(vb.z, vb.w);
        int off = toff(row, kg);
        *(uint4*)(smem + OFF_A + off) =
            make_uint4(*(u32*)&h0, *(u32*)&h1, *(u32*)&h2, *(u32*)&h3);
    }
    // ---- per-edge preprocess (sin recurrence for RBF) ----
    if (tid < TM) {
        int e = tid;
        if (e < nvalid) {
            long eg = e0 + e;
            float r0 = r_iI[eg * 3 + 0], r1 = r_iI[eg * 3 + 1], r2 = r_iI[eg * 3 + 2];
            float d = sqrtf(r0 * r0 + r1 * r1 + r2 * r2 + 3e-8f);
            float id = 1.0f / d;
            sUnit[0 * 128 + e] = r0 * id;
            sUnit[1 * 128 + e] = r1 * id;
            sUnit[2 * 128 + e] = r2 * id;
            sEnv[e] = (d < 5.0f) ? 0.5f * (cosf(PI_OVER_CUT * d) + 1.0f) : 0.0f;
            float theta = PI_OVER_CUT * d;
            float s1, c1;
            sincosf(theta, &s1, &c1);
            float twoc = 2.0f * c1;
            float sp = 0.0f, sn = s1;            // sin(0), sin(theta)
            #pragma unroll
            for (int n = 0; n < NRBF; n++) {
                sRbfT[n * 128 + e] = sn * id;
                float nx = twoc * sn - sp;       // sin((n+2)theta)
                sp = sn; sn = nx;
            }
            int b = mapping[eg];
            sBin[e] = b;
            atomicAdd(&g_cnt[b], 1.0f);
        } else {
            sUnit[e] = sUnit[128 + e] = sUnit[256 + e] = 0.0f;
            sEnv[e] = 0.0f; sBin[e] = 0;
            #pragma unroll
            for (int n = 0; n < NRBF; n++) sRbfT[n * 128 + e] = 0.0f;
        }
    }
    cpa_wait0();
    __syncthreads();

    float acc[16][4];
    float st0[16][4];

    // ---- GEMM1 ----
    #pragma unroll
    for (int q = 0; q < 16; q++)
        acc[q][0] = acc[q][1] = acc[q][2] = acc[q][3] = 0.0f;
    gemm_tile(sb + OFF_A, sb + OFF_W, m0, lane, acc);
    __syncthreads();                  // all warps done reading W1
    copyW_async(sb, g_W2, tid);       // prefetch W2[0] under dump+silu
    dump_all(sScr, acc, m0, lane);
    __syncwarp();

    // ---- silu(D1 + b1) -> H fp16 (own warp's rows) ----
    {
        const int j0  = (tid & 31) * 4;
        const int ebl = (tid >> 5) * 16;
        float4 bb = *(const float4*)&b1[j0];
        #pragma unroll 4
        for (int e = 0; e < 16; e++) {
            int ei = ebl + e;
            float4 d = *(float4*)&sScr[scr_w(ei, j0)];
            float x0 = d.x + bb.x, x1 = d.y + bb.y, x2 = d.z + bb.z, x3 = d.w + bb.w;
            float s0 = x0 / (1.0f + __expf(-x0));
            float s1 = x1 / (1.0f + __expf(-x1));
            float s2 = x2 / (1.0f + __expf(-x2));
            float s3 = x3 / (1.0f + __expf(-x3));
            __half2 hA = __floats2half2_rn(s0, s1);
            __half2 hB = __floats2half2_rn(s2, s3);
            int off = toff(ei, j0 >> 3) + (j0 & 7) * 2;
            *(uint2*)(smem + OFF_A + off) = make_uint2(*(u32*)&hA, *(u32*)&hB);
        }
    }
    cpa_wait0();
    __syncthreads();   // H + W2[0] ready

    // ---- GEMM2 chunk 0 ----
    #pragma unroll
    for (int q = 0; q < 16; q++)
        acc[q][0] = acc[q][1] = acc[q][2] = acc[q][3] = 0.0f;
    gemm_tile(sb + OFF_A, sb + OFF_W, m0, lane, acc);
    __syncthreads();
    copyW_async(sb, g_W2 + 32768, tid);
    dump_all(sScr, acc, m0, lane);
    __syncwarp();
    epilogue<0>(sScr, sRbfT, sUnit, sEnv, sBin, v_i, Wr_g, b2, br,
                e0, nvalid, tid, st0);
    cpa_wait0();
    __syncthreads();

    // ---- GEMM2 chunk 1 ----
    #pragma unroll
    for (int q = 0; q < 16; q++)
        acc[q][0] = acc[q][1] = acc[q][2] = acc[q][3] = 0.0f;
    gemm_tile(sb + OFF_A, sb + OFF_W, m0, lane, acc);
    __syncthreads();
    copyW_async(sb, g_W2 + 65536, tid);
    dump_all(sScr, acc, m0, lane);
    __syncwarp();
    epilogue<1>(sScr, sRbfT, sUnit, sEnv, sBin, v_i, Wr_g, b2, br,
                e0, nvalid, tid, st0);
    cpa_wait0();
    __syncthreads();

    // ---- GEMM2 chunk 2 ----
    #pragma unroll
    for (int q = 0; q < 16; q++)
        acc[q][0] = acc[q][1] = acc[q][2] = acc[q][3] = 0.0f;
    gemm_tile(sb + OFF_A, sb + OFF_W, m0, lane, acc);
    dump_all(sScr, acc, m0, lane);
    __syncwarp();
    epilogue<2>(sScr, sRbfT, sUnit, sEnv, sBin, v_i, Wr_g, b2, br,
                e0, nvalid, tid, st0);
}

__global__ void cmb_final(float* __restrict__ out) {
    int bin = blockIdx.x;
    int f   = threadIdx.x;
    float ic = 1.0f / fmaxf(g_cnt[bin], 1.0f);
    out[bin * FEAT + f] = g_acc_s[bin * FEAT + f] * ic;
    #pragma unroll
    for (int x = 0; x < 3; x++)
        out[NB * FEAT + bin * 384 + f * 3 + x] =
            g_acc_v[bin * 3 * FEAT + x * FEAT + f] * ic;
}

extern "C" void kernel_launch(void* const* d_in, const int* in_sizes, int n_in,
                              void* d_out, int out_size)
{
    const float* s_i     = (const float*)d_in[0];
    const float* v_i     = (const float*)d_in[1];
    const float* r_iI    = (const float*)d_in[2];
    const float* W1      = (const float*)d_in[3];
    const float* b1      = (const float*)d_in[4];
    const float* W2      = (const float*)d_in[5];
    const float* b2      = (const float*)d_in[6];
    const float* Wr      = (const float*)d_in[7];
    const float* br      = (const float*)d_in[8];
    const int*   mapping = (const int*)d_in[9];
    float* out = (float*)d_out;
    (void)in_sizes; (void)n_in; (void)out_size;

    cudaFuncSetAttribute((const void*)cmb_main,
                         cudaFuncAttributeMaxDynamicSharedMemorySize, SMEM_BYTES);

    cmb_prep<<<256, 256>>>(W1, W2);
    cmb_zero<<<(NB * 3 * FEAT + 255) / 256, 256>>>();
    cmb_main<<<NBLK, 256, SMEM_BYTES>>>(s_i, v_i, r_iI, b1, b2, Wr, br, mapping);
    cmb_final<<<NB, FEAT>>>(out);
}

// round 10
// speedup vs baseline: 1.2827x; 1.0535x over previous
#include <cuda_runtime.h>
#include <cuda_fp16.h>
#include <math.h>

// ContractiveMessageBlock — Round 9: single-pass fp16 HMMA + warp free-running.
// All three W2 chunks resident in smem; only 3 block barriers; warps overlap
// GEMM (tensor) with epilogue (LSU/FMA) across the chunk pipeline.

#define E_TOT   200000
#define FEAT    128
#define TM      128
#define NBLK    ((E_TOT + TM - 1) / TM)   // 1563
#define NB      2000
#define NRBF    20
#define PI_OVER_CUT 0.62831853071795864769f

typedef unsigned long long u64;
typedef unsigned int u32;

// ---------------- f32x2 / misc helpers ----------------
__device__ __forceinline__ u64 fma2(u64 a, u64 b, u64 c) {
    u64 d; asm("fma.rn.f32x2 %0, %1, %2, %3;" : "=l"(d) : "l"(a), "l"(b), "l"(c)); return d;
}
__device__ __forceinline__ u64 mul2(u64 a, u64 b) {
    u64 d; asm("mul.rn.f32x2 %0, %1, %2;" : "=l"(d) : "l"(a), "l"(b)); return d;
}
__device__ __forceinline__ u64 add2(u64 a, u64 b) {
    u64 d; asm("add.rn.f32x2 %0, %1, %2;" : "=l"(d) : "l"(a), "l"(b)); return d;
}
__device__ __forceinline__ u64 dup2(float x) {
    u64 d; asm("mov.b64 %0, {%1, %1};" : "=l"(d) : "f"(x)); return d;
}
__device__ __forceinline__ u64 pk2(float a, float b) {
    u64 d; asm("mov.b64 %0, {%1, %2};" : "=l"(d) : "f"(a), "f"(b)); return d;
}
__device__ __forceinline__ void unpack2(u64 a, float& lo, float& hi) {
    asm("mov.b64 {%0, %1}, %2;" : "=f"(lo), "=f"(hi) : "l"(a));
}
__device__ __forceinline__ void red_add_v4(float* p, float a, float b, float c, float d) {
    asm volatile("red.global.add.v4.f32 [%0], {%1, %2, %3, %4};"
                 :: "l"(p), "f"(a), "f"(b), "f"(c), "f"(d) : "memory");
}
__device__ __forceinline__ u32 smem_u32(const void* p) {
    u32 a; asm("{ .reg .u64 t; cvta.to.shared.u64 t, %1; cvt.u32.u64 %0, t; }"
               : "=r"(a) : "l"(p));
    return a;
}
__device__ __forceinline__ void cpa16(u32 s, const void* g) {
    asm volatile("cp.async.cg.shared.global [%0], [%1], 16;" :: "r"(s), "l"(g));
}
__device__ __forceinline__ void cpa_commit() {
    asm volatile("cp.async.commit_group;" ::: "memory");
}
__device__ __forceinline__ void cpa_wait0() {
    asm volatile("cp.async.wait_group 0;" ::: "memory");
}

// ---------------- mma / ldmatrix ----------------
__device__ __forceinline__ void ldsm4(u32* r, u32 addr) {
    asm volatile("ldmatrix.sync.aligned.m8n8.x4.shared.b16 {%0,%1,%2,%3}, [%4];"
                 : "=r"(r[0]), "=r"(r[1]), "=r"(r[2]), "=r"(r[3]) : "r"(addr));
}
__device__ __forceinline__ void mma16816(float* d, const u32* a, u32 b0, u32 b1) {
    asm volatile(
        "mma.sync.aligned.m16n8k16.row.col.f32.f16.f16.f32 "
        "{%0,%1,%2,%3}, {%4,%5,%6,%7}, {%8,%9}, {%0,%1,%2,%3};"
        : "+f"(d[0]), "+f"(d[1]), "+f"(d[2]), "+f"(d[3])
        : "r"(a[0]), "r"(a[1]), "r"(a[2]), "r"(a[3]), "r"(b0), "r"(b1));
}

// fp16 tile [128 rows][128 k]: 16B granules, XOR swizzle.
__device__ __host__ __forceinline__ int toff(int row, int kg) {
    return row * 256 + (((kg ^ (row & 7)) & 15) << 4);
}
// fp32 scratch [128 e][128 c], word index with 4-word-granule XOR swizzle.
__device__ __forceinline__ int scr_w(int e, int c) {
    return e * 128 + (((((c >> 2)) ^ (e & 7)) & 31) << 2) + (c & 3);
}

// ---------------- global scratch ----------------
__device__ __align__(16) float g_acc_s[NB * FEAT];      // [bin][f]
__device__ __align__(16) float g_acc_v[NB * 3 * FEAT];  // [bin][x][f]
__device__ float g_cnt[NB];
__device__ __align__(16) unsigned char g_W1[32768];          // fp16 tile
__device__ __align__(16) unsigned char g_W2[3 * 32768];      // fp16 tiles

// ---------------- smem offsets (bytes) ----------------
#define OFF_A    0        // 32768  A then H, fp16
#define OFF_WS0  32768    // 32768  W1, later W2 chunk2
#define OFF_WS1  65536    // 32768  W2 chunk0
#define OFF_WS2  98304    // 32768  W2 chunk1
#define OFF_SCR  131072   // 65536  fp32 D dump [128][128] (per-warp stripes)
#define OFF_RBF  196608   // 10240  rbf [20][128]
#define OFF_UNIT 206848   // 1536   unit [3][128]
#define OFF_ENV  208384   // 512
#define OFF_BIN  208896   // 512 (int)
#define SMEM_BYTES 209408

__global__ void cmb_zero() {
    int i = blockIdx.x * 256 + threadIdx.x;
    if (i < NB * FEAT)     g_acc_s[i] = 0.0f;
    if (i < NB * 3 * FEAT) g_acc_v[i] = 0.0f;
    if (i < NB)            g_cnt[i]   = 0.0f;
}

// W1/W2 -> fp16 tiles in swizzled [n][k] layout (B operand, TN gemm).
__global__ void cmb_prep(const float* __restrict__ W1, const float* __restrict__ W2) {
    int i = blockIdx.x * 256 + threadIdx.x;     // 0..65535
    if (i < 16384) {
        int n = i & 127, k = i >> 7;
        float v = W1[k * 128 + n];
        int off = toff(n, k >> 3) + (k & 7) * 2;
        *(__half*)(g_W1 + off) = __float2half_rn(v);
    } else if (i < 65536) {
        int r = i - 16384;
        int c = r >> 14;
        int t = r & 16383;
        int n = t & 127, k = t >> 7;
        float v = W2[k * 384 + c * 128 + n];
        int off = c * 32768 + toff(n, k >> 3) + (k & 7) * 2;
        *(__half*)(g_W2 + off) = __float2half_rn(v);
    }
}

// Issue cp.async for one 32KB W tile into the given smem slot.
__device__ __forceinline__ void copyW_async(u32 dst, const unsigned char* g, int tid) {
    #pragma unroll
    for (int t = 0; t < 8; t++) {
        int i = tid + t * 256;
        cpa16(dst + i * 16, g + i * 16);
    }
}

// Single-pass fp16 GEMM: acc += A * B over warp stripe. 128 HMMA per call.
__device__ __forceinline__ void gemm_tile(u32 aT, u32 bW,
                                          int m0, int lane, float acc[16][4]) {
    const int r  = lane & 7;
    const int hf = (lane >> 3) & 1;
    const int kq = lane >> 4;
    const int arow = m0 + hf * 8 + r;
    const int brow = hf * 8 + r;
    #pragma unroll
    for (int ks = 0; ks < 8; ks++) {
        int kg = ks * 2 + kq;
        u32 a[4];
        ldsm4(a, aT + (u32)toff(arow, kg));
        #pragma unroll
        for (int ng = 0; ng < 8; ng++) {
            u32 b[4];
            ldsm4(b, bW + (u32)toff(ng * 16 + brow, kg));
            mma16816(acc[2 * ng],     a, b[0], b[2]);
            mma16816(acc[2 * ng + 1], a, b[1], b[3]);
        }
    }
}

__device__ __forceinline__ void dump_all(float* scr, const float acc[16][4],
                                         int m0, int lane) {
    const int r0 = m0 + (lane >> 2);
    const int cb = (lane & 3) * 2;
    #pragma unroll
    for (int ng = 0; ng < 8; ng++)
        #pragma unroll
        for (int s = 0; s < 2; s++) {
            int c = ng * 16 + s * 8 + cb;
            const float* a = acc[2 * ng + s];
            *(float2*)&scr[scr_w(r0, c)]     = make_float2(a[0], a[1]);
            *(float2*)&scr[scr_w(r0 + 8, c)] = make_float2(a[2], a[3]);
        }
}

// Fused epilogue for chunk C. Fully unrolled over 16 edges so st0 stays in regs.
template <int C>
__device__ __forceinline__ void epilogue(
    const float* sScr, const float* sRbfT, const float* sUnit,
    const float* sEnv, const int* sBin,
    const float* __restrict__ v_i, const float* __restrict__ Wr_g,
    const float* __restrict__ b2, const float* __restrict__ br,
    long e0, int nvalid, int tid, float st0[16][4])
{
    const int j0  = (tid & 31) * 4;
    const int ebl = (tid >> 5) * 16;
    u64 wra[NRBF], wrb[NRBF];
    #pragma unroll
    for (int n = 0; n < NRBF; n++) {
        float4 w = *(const float4*)&Wr_g[n * 384 + C * 128 + j0];
        wra[n] = pk2(w.x, w.y); wrb[n] = pk2(w.z, w.w);
    }
    float4 b2v = *(const float4*)&b2[C * 128 + j0];
    float4 brv = *(const float4*)&br[C * 128 + j0];
    u64 b2a = pk2(b2v.x, b2v.y), b2b = pk2(b2v.z, b2v.w);
    u64 bra = pk2(brv.x, brv.y), brb = pk2(brv.z, brv.w);

    #pragma unroll
    for (int e = 0; e < 16; e++) {
        int ei = ebl + e;
        u64 w0 = bra, w1 = brb;
        #pragma unroll
        for (int n = 0; n < NRBF; n++) {
            u64 f = dup2(sRbfT[n * 128 + ei]);
            w0 = fma2(f, wra[n], w0);
            w1 = fma2(f, wrb[n], w1);
        }
        float4 d = *(const float4*)&sScr[scr_w(ei, j0)];
        u64 envd = dup2(sEnv[ei]);
        u64 i01 = mul2(add2(pk2(d.x, d.y), b2a), mul2(w0, envd));
        u64 i23 = mul2(add2(pk2(d.z, d.w), b2b), mul2(w1, envd));
        float i0, i1, i2, i3;
        unpack2(i01, i0, i1); unpack2(i23, i2, i3);

        if (C == 0) {
            st0[e][0] = i0; st0[e][1] = i1; st0[e][2] = i2; st0[e][3] = i3;
        } else if (C == 1) {
            if (ei < nvalid) {
                int bin = sBin[ei];
                red_add_v4(&g_acc_s[bin * FEAT + j0], i0, i1, i2, i3);
            }
        } else {
            if (ei < nvalid) {
                int bin = sBin[ei];
                const float4* vg =
                    (const float4*)(v_i + ((size_t)(e0 + ei) * FEAT + j0) * 3);
                float4 va = vg[0], vb = vg[1], vc2 = vg[2];
                float vf[12] = { va.x, va.y, va.z, va.w,
                                 vb.x, vb.y, vb.z, vb.w,
                                 vc2.x, vc2.y, vc2.z, vc2.w };
                float uu[3] = { sUnit[ei], sUnit[128 + ei], sUnit[256 + ei] };
                #pragma unroll
                for (int x = 0; x < 3; x++)
                    red_add_v4(&g_acc_v[bin * 3 * FEAT + x * FEAT + j0],
                        fmaf(i0, uu[x], st0[e][0] * vf[0 + x]),
                        fmaf(i1, uu[x], st0[e][1] * vf[3 + x]),
                        fmaf(i2, uu[x], st0[e][2] * vf[6 + x]),
                        fmaf(i3, uu[x], st0[e][3] * vf[9 + x]));
            }
        }
    }
}

__global__ void __launch_bounds__(256, 1)
cmb_main(const float* __restrict__ s_i, const float* __restrict__ v_i,
         const float* __restrict__ r_iI, const float* __restrict__ b1,
         const float* __restrict__ b2, const float* __restrict__ Wr_g,
         const float* __restrict__ br, const int* __restrict__ mapping)
{
    extern __shared__ char smem[];
    const u32 sb = smem_u32(smem);
    float* sScr  = (float*)(smem + OFF_SCR);
    float* sRbfT = (float*)(smem + OFF_RBF);
    float* sUnit = (float*)(smem + OFF_UNIT);
    float* sEnv  = (float*)(smem + OFF_ENV);
    int*   sBin  = (int*)(smem + OFF_BIN);

    const int tid  = threadIdx.x;
    const int lane = tid & 31;
    const int m0   = (tid >> 5) * 16;
    const long e0  = (long)blockIdx.x * TM;
    const int nvalid = (int)min((long)TM, (long)E_TOT - e0);

    // ---- prefetch W1 + W2 chunk0 + chunk1 (one cp.async group) ----
    copyW_async(sb + OFF_WS0, g_W1, tid);
    copyW_async(sb + OFF_WS1, g_W2, tid);
    copyW_async(sb + OFF_WS2, g_W2 + 32768, tid);
    cpa_commit();

    // ---- A tile: s_i -> fp16 swizzled ----
    for (int i = tid; i < 2048; i += 256) {
        int row = i >> 4, kg = i & 15;
        float4 va, vb;
        if (row < nvalid) {
            const float4* g = (const float4*)(s_i + ((size_t)(e0 + row)) * FEAT + kg * 8);
            va = g[0]; vb = g[1];
        } else {
            va = make_float4(0.f, 0.f, 0.f, 0.f); vb = va;
        }
        __half2 h0 = __floats2half2_rn(va.x, va.y);
        __half2 h1 = __floats2half2_rn(va.z, va.w);
        __half2 h2 = __floats2half2_rn(vb.x, vb.y);
        __half2 h3 = __floats2half2_rn(vb.z, vb.w);
        int off = toff(row, kg);
        *(uint4*)(smem + OFF_A + off) =
            make_uint4(*(u32*)&h0, *(u32*)&h1, *(u32*)&h2, *(u32*)&h3);
    }
    // ---- per-edge preprocess (sin recurrence for RBF) ----
    if (tid < TM) {
        int e = tid;
        if (e < nvalid) {
            long eg = e0 + e;
            float r0 = r_iI[eg * 3 + 0], r1 = r_iI[eg * 3 + 1], r2 = r_iI[eg * 3 + 2];
            float d = sqrtf(r0 * r0 + r1 * r1 + r2 * r2 + 3e-8f);
            float id = 1.0f / d;
            sUnit[0 * 128 + e] = r0 * id;
            sUnit[1 * 128 + e] = r1 * id;
            sUnit[2 * 128 + e] = r2 * id;
            sEnv[e] = (d < 5.0f) ? 0.5f * (cosf(PI_OVER_CUT * d) + 1.0f) : 0.0f;
            float theta = PI_OVER_CUT * d;
            float s1, c1;
            sincosf(theta, &s1, &c1);
            float twoc = 2.0f * c1;
            float sp = 0.0f, sn = s1;            // sin(0), sin(theta)
            #pragma unroll
            for (int n = 0; n < NRBF; n++) {
                sRbfT[n * 128 + e] = sn * id;
                float nx = twoc * sn - sp;       // sin((n+2)theta)
                sp = sn; sn = nx;
            }
            int b = mapping[eg];
            sBin[e] = b;
            atomicAdd(&g_cnt[b], 1.0f);
        } else {
            sUnit[e] = sUnit[128 + e] = sUnit[256 + e] = 0.0f;
            sEnv[e] = 0.0f; sBin[e] = 0;
            #pragma unroll
            for (int n = 0; n < NRBF; n++) sRbfT[n * 128 + e] = 0.0f;
        }
    }
    cpa_wait0();
    __syncthreads();        // barrier 1: A, W1, c0, c1, preprocess all visible

    float acc[16][4];
    float st0[16][4];

    // ---- GEMM1 (W1 in slot0) ----
    #pragma unroll
    for (int q = 0; q < 16; q++)
        acc[q][0] = acc[q][1] = acc[q][2] = acc[q][3] = 0.0f;
    gemm_tile(sb + OFF_A, sb + OFF_WS0, m0, lane, acc);
    __syncthreads();        // barrier 2: all warps done reading slot0 (W1)

    // prefetch W2 chunk2 into slot0 — arrival fenced by barrier 3 below
    copyW_async(sb + OFF_WS0, g_W2 + 65536, tid);
    cpa_commit();

    // ---- from here warps FREE-RUN until barrier 3 ----
    dump_all(sScr, acc, m0, lane);
    __syncwarp();

    // ---- silu(D1 + b1) -> H fp16 (own warp's rows only) ----
    {
        const int j0  = (tid & 31) * 4;
        const int ebl = (tid >> 5) * 16;
        float4 bb = *(const float4*)&b1[j0];
        #pragma unroll 4
        for (int e = 0; e < 16; e++) {
            int ei = ebl + e;
            float4 d = *(float4*)&sScr[scr_w(ei, j0)];
            float x0 = d.x + bb.x, x1 = d.y + bb.y, x2 = d.z + bb.z, x3 = d.w + bb.w;
            float s0 = x0 / (1.0f + __expf(-x0));
            float s1 = x1 / (1.0f + __expf(-x1));
            float s2 = x2 / (1.0f + __expf(-x2));
            float s3 = x3 / (1.0f + __expf(-x3));
            __half2 hA = __floats2half2_rn(s0, s1);
            __half2 hB = __floats2half2_rn(s2, s3);
            int off = toff(ei, j0 >> 3) + (j0 & 7) * 2;
            *(uint2*)(smem + OFF_A + off) = make_uint2(*(u32*)&hA, *(u32*)&hB);
        }
    }
    __syncwarp();           // warp-local H visible to own ldmatrix

    // ---- GEMM2 chunk 0 (slot1) + epilogue<0> ----
    #pragma unroll
    for (int q = 0; q < 16; q++)
        acc[q][0] = acc[q][1] = acc[q][2] = acc[q][3] = 0.0f;
    gemm_tile(sb + OFF_A, sb + OFF_WS1, m0, lane, acc);
    dump_all(sScr, acc, m0, lane);
    __syncwarp();
    epilogue<0>(sScr, sRbfT, sUnit, sEnv, sBin, v_i, Wr_g, b2, br,
                e0, nvalid, tid, st0);

    // ---- GEMM2 chunk 1 (slot2) + epilogue<1> ----
    #pragma unroll
    for (int q = 0; q < 16; q++)
        acc[q][0] = acc[q][1] = acc[q][2] = acc[q][3] = 0.0f;
    gemm_tile(sb + OFF_A, sb + OFF_WS2, m0, lane, acc);
    dump_all(sScr, acc, m0, lane);
    __syncwarp();
    epilogue<1>(sScr, sRbfT, sUnit, sEnv, sBin, v_i, Wr_g, b2, br,
                e0, nvalid, tid, st0);

    // ---- barrier 3: c2 arrived in slot0 (all threads' cp.asyncs drained) ----
    cpa_wait0();
    __syncthreads();

    // ---- GEMM2 chunk 2 (slot0) + epilogue<2> ----
    #pragma unroll
    for (int q = 0; q < 16; q++)
        acc[q][0] = acc[q][1] = acc[q][2] = acc[q][3] = 0.0f;
    gemm_tile(sb + OFF_A, sb + OFF_WS0, m0, lane, acc);
    dump_all(sScr, acc, m0, lane);
    __syncwarp();
    epilogue<2>(sScr, sRbfT, sUnit, sEnv, sBin, v_i, Wr_g, b2, br,
                e0, nvalid, tid, st0);
}

__global__ void cmb_final(float* __restrict__ out) {
    int bin = blockIdx.x;
    int f   = threadIdx.x;
    float ic = 1.0f / fmaxf(g_cnt[bin], 1.0f);
    out[bin * FEAT + f] = g_acc_s[bin * FEAT + f] * ic;
    #pragma unroll
    for (int x = 0; x < 3; x++)
        out[NB * FEAT + bin * 384 + f * 3 + x] =
            g_acc_v[bin * 3 * FEAT + x * FEAT + f] * ic;
}

extern "C" void kernel_launch(void* const* d_in, const int* in_sizes, int n_in,
                              void* d_out, int out_size)
{
    const float* s_i     = (const float*)d_in[0];
    const float* v_i     = (const float*)d_in[1];
    const float* r_iI    = (const float*)d_in[2];
    const float* W1      = (const float*)d_in[3];
    const float* b1      = (const float*)d_in[4];
    const float* W2      = (const float*)d_in[5];
    const float* b2      = (const float*)d_in[6];
    const float* Wr      = (const float*)d_in[7];
    const float* br      = (const float*)d_in[8];
    const int*   mapping = (const int*)d_in[9];
    float* out = (float*)d_out;
    (void)in_sizes; (void)n_in; (void)out_size;

    cudaFuncSetAttribute((const void*)cmb_main,
                         cudaFuncAttributeMaxDynamicSharedMemorySize, SMEM_BYTES);

    cmb_prep<<<256, 256>>>(W1, W2);
    cmb_zero<<<(NB * 3 * FEAT + 255) / 256, 256>>>();
    cmb_main<<<NBLK, 256, SMEM_BYTES>>>(s_i, v_i, r_iI, b1, b2, Wr, br, mapping);
    cmb_final<<<NB, FEAT>>>(out);
}